// round 16
// baseline (speedup 1.0000x reference)
#include <cuda_runtime.h>
#include <cuda_bf16.h>
#include <cstdint>

#define NN 50000
#define EE 800000

// Scratch state (device globals: allocation-free)
__device__ float g_h[NN * 64];
__device__ float g_h2[NN * 64];
__device__ float g_p[NN * 64];
__device__ float g_U[NN * 64];
__device__ float g_V[NN * 64];
__device__ float g_A[NN * 64];
__device__ float g_agg[NN * 64];
__device__ float g_Sagg[NN * 16];
__device__ int   g_deg[NN];
__device__ float g_Gall[4 * 17 * 64];   // per-layer h-msg composed edge weight
__device__ float g_G2all[4 * 17 * 64];  // per-layer p-msg composed edge weight
__device__ float g_CW[4 * 4 * 4096];    // [l][m][64x64]: m=0 WaE1,1 WbE1,2 WaE2,3 WbE2
__device__ float g_CB[4 * 2 * 64];      // [l][0]=bU, [l][1]=bV
__device__ float g_zero64[64];          // stays zero

struct Chunk {
    const float* X;   // row base
    int stride;       // row stride in floats
    const float* W;   // 64x64 weight chunk, row-major
};

struct Job {
    Chunk c0, c1, c2;
    const float* bias;
    float* out;
    int nchunk;
};

__device__ __forceinline__ void split_bf16(float x, __nv_bfloat16& hi, __nv_bfloat16& lo) {
    hi = __float2bfloat16_rn(x);
    lo = __float2bfloat16_rn(x - __bfloat162float(hi));
}

#define MMAB(d, a0, a1, a2, a3, b0, b1)                                       \
    asm volatile(                                                             \
        "mma.sync.aligned.m16n8k16.row.col.f32.bf16.bf16.f32 "                \
        "{%0,%1,%2,%3}, {%4,%5,%6,%7}, {%8,%9}, {%0,%1,%2,%3};"               \
        : "+f"(d[0]), "+f"(d[1]), "+f"(d[2]), "+f"(d[3])                      \
        : "r"(a0), "r"(a1), "r"(a2), "r"(a3), "r"(b0), "r"(b1))

// ---------------------------------------------------------------------------
// Multi-job node GEMM, 3xBF16 (near-fp32): blockIdx.y selects job (up to 3).
//   out[row](64) = sum_c X_c[row](64) @ W_c + bias
// If EPI_AGG, job 1's epilogue instead writes:
//   out[r][c] = deg[r]*(acc[r][c] + G[16][c]) + Sagg[r](16) @ G[0:16][c]
// CTA 256 rows x 64 cols, 8 warps; warp tile 32 rows x 64 cols (m16n8k16).
template <int EPI_AGG>
__global__ void __launch_bounds__(256, 2) mjgemm_kernel(
    Job j0, Job j1, Job j2,
    const float* __restrict__ Sagg, const float* __restrict__ Gmat,
    const int* __restrict__ deg, int nrows)
{
    extern __shared__ char dynraw[];
    __nv_bfloat16* Xhi = (__nv_bfloat16*)dynraw;     // [256][72]
    __nv_bfloat16* Xlo = Xhi + 256 * 72;
    __nv_bfloat16* Whi = Xlo + 256 * 72;             // [col][k]: [64][72]
    __nv_bfloat16* Wlo = Whi + 64 * 72;
    __shared__ float bs[64];

    const Job& J = (blockIdx.y == 0) ? j0 : ((blockIdx.y == 1) ? j1 : j2);
    const bool doEpi = EPI_AGG && (blockIdx.y == 1);

    const int tid = threadIdx.x;
    const int row0 = blockIdx.x * 256;
    const int lane = tid & 31;
    const int warp = tid >> 5;
    const int warpRow0 = warp * 32;
    const int qrow = lane >> 2;   // 0..7
    const int qk = lane & 3;      // 0..3

    if (tid < 64) bs[tid] = J.bias[tid];

    float acc[2][8][4];
    #pragma unroll
    for (int mt = 0; mt < 2; mt++)
        #pragma unroll
        for (int nt = 0; nt < 8; nt++)
            #pragma unroll
            for (int r = 0; r < 4; r++) acc[mt][nt][r] = 0.0f;

    const Chunk chunks[3] = {J.c0, J.c1, J.c2};
    const int nchunk = J.nchunk;

    // W loader mapping: coalesced (lane = col), 16 k's per thread
    const int wcol = tid & 63;
    const int wkb = (tid >> 6) * 16;

    for (int c = 0; c < 3; c++) {
        if (c >= nchunk) break;
        const float* Xb = chunks[c].X;
        const int stride = chunks[c].stride;
        const float* wpb = chunks[c].W;

        __syncthreads();
        // X: 256 rows x 64 floats; coalesced
        #pragma unroll
        for (int i = 0; i < 16; i++) {
            const int g = tid + 256 * i;
            const int row = g >> 4;
            const int f = (g & 15) * 4;
            int grow = row0 + row;
            if (grow > nrows - 1) grow = nrows - 1;
            float4 v = *(const float4*)(Xb + (size_t)grow * stride + f);
            __nv_bfloat16 h0, l0, h1, l1, h2, l2, h3, l3;
            split_bf16(v.x, h0, l0);
            split_bf16(v.y, h1, l1);
            split_bf16(v.z, h2, l2);
            split_bf16(v.w, h3, l3);
            __nv_bfloat162* ph = (__nv_bfloat162*)(Xhi + row * 72 + f);
            __nv_bfloat162* pl = (__nv_bfloat162*)(Xlo + row * 72 + f);
            ph[0] = __nv_bfloat162{h0, h1};
            ph[1] = __nv_bfloat162{h2, h3};
            pl[0] = __nv_bfloat162{l0, l1};
            pl[1] = __nv_bfloat162{l2, l3};
        }
        // W: store transposed [col][k]
        #pragma unroll
        for (int j = 0; j < 16; j += 2) {
            float x0 = wpb[(size_t)(wkb + j) * 64 + wcol];
            float x1 = wpb[(size_t)(wkb + j + 1) * 64 + wcol];
            __nv_bfloat16 h0, l0, h1, l1;
            split_bf16(x0, h0, l0);
            split_bf16(x1, h1, l1);
            *(__nv_bfloat162*)(Whi + wcol * 72 + wkb + j) = __nv_bfloat162{h0, h1};
            *(__nv_bfloat162*)(Wlo + wcol * 72 + wkb + j) = __nv_bfloat162{l0, l1};
        }
        __syncthreads();

        #pragma unroll
        for (int ks = 0; ks < 4; ks++) {
            const int k0 = ks * 16;
            uint32_t ah[2][4], al[2][4];
            #pragma unroll
            for (int mt = 0; mt < 2; mt++) {
                const int r = warpRow0 + mt * 16 + qrow;
                ah[mt][0] = *(const uint32_t*)(Xhi + r * 72 + k0 + 2 * qk);
                ah[mt][1] = *(const uint32_t*)(Xhi + (r + 8) * 72 + k0 + 2 * qk);
                ah[mt][2] = *(const uint32_t*)(Xhi + r * 72 + k0 + 2 * qk + 8);
                ah[mt][3] = *(const uint32_t*)(Xhi + (r + 8) * 72 + k0 + 2 * qk + 8);
                al[mt][0] = *(const uint32_t*)(Xlo + r * 72 + k0 + 2 * qk);
                al[mt][1] = *(const uint32_t*)(Xlo + (r + 8) * 72 + k0 + 2 * qk);
                al[mt][2] = *(const uint32_t*)(Xlo + r * 72 + k0 + 2 * qk + 8);
                al[mt][3] = *(const uint32_t*)(Xlo + (r + 8) * 72 + k0 + 2 * qk + 8);
            }
            #pragma unroll
            for (int nt = 0; nt < 8; nt++) {
                const int col = nt * 8 + qrow;
                uint32_t bh0 = *(const uint32_t*)(Whi + col * 72 + k0 + 2 * qk);
                uint32_t bh1 = *(const uint32_t*)(Whi + col * 72 + k0 + 2 * qk + 8);
                uint32_t bl0 = *(const uint32_t*)(Wlo + col * 72 + k0 + 2 * qk);
                uint32_t bl1 = *(const uint32_t*)(Wlo + col * 72 + k0 + 2 * qk + 8);
                #pragma unroll
                for (int mt = 0; mt < 2; mt++) {
                    MMAB(acc[mt][nt], ah[mt][0], ah[mt][1], ah[mt][2], ah[mt][3], bh0, bh1);
                    MMAB(acc[mt][nt], ah[mt][0], ah[mt][1], ah[mt][2], ah[mt][3], bl0, bl1);
                    MMAB(acc[mt][nt], al[mt][0], al[mt][1], al[mt][2], al[mt][3], bh0, bh1);
                }
            }
        }
    }

    if (doEpi) {
        float* Gs = (float*)Xhi;
        __syncthreads();
        for (int i = tid; i < 17 * 64; i += 256) Gs[i] = Gmat[i];
        __syncthreads();
        #pragma unroll
        for (int mt = 0; mt < 2; mt++) {
            #pragma unroll
            for (int half = 0; half < 2; half++) {
                const int r = warpRow0 + mt * 16 + qrow + half * 8;
                const int grow = row0 + r;
                if (grow < nrows) {
                    const float dg = (float)deg[grow];
                    float sg[16];
                    const float4* sp = (const float4*)(Sagg + (size_t)grow * 16);
                    #pragma unroll
                    for (int q = 0; q < 4; q++) {
                        float4 v = sp[q];
                        sg[4 * q] = v.x; sg[4 * q + 1] = v.y;
                        sg[4 * q + 2] = v.z; sg[4 * q + 3] = v.w;
                    }
                    #pragma unroll
                    for (int nt = 0; nt < 8; nt++) {
                        const int col = nt * 8 + 2 * qk;
                        float v0 = dg * (acc[mt][nt][half * 2 + 0] + Gs[16 * 64 + col]);
                        float v1 = dg * (acc[mt][nt][half * 2 + 1] + Gs[16 * 64 + col + 1]);
                        #pragma unroll
                        for (int k = 0; k < 16; k++) {
                            v0 += sg[k] * Gs[k * 64 + col];
                            v1 += sg[k] * Gs[k * 64 + col + 1];
                        }
                        *(float2*)(J.out + (size_t)grow * 64 + col) = make_float2(v0, v1);
                    }
                }
            }
        }
    } else {
        #pragma unroll
        for (int mt = 0; mt < 2; mt++) {
            #pragma unroll
            for (int half = 0; half < 2; half++) {
                const int r = warpRow0 + mt * 16 + qrow + half * 8;
                const int grow = row0 + r;
                if (grow < nrows) {
                    #pragma unroll
                    for (int nt = 0; nt < 8; nt++) {
                        const int col = nt * 8 + 2 * qk;
                        float v0 = acc[mt][nt][half * 2 + 0] + bs[col];
                        float v1 = acc[mt][nt][half * 2 + 1] + bs[col + 1];
                        *(float2*)(J.out + (size_t)grow * 64 + col) = make_float2(v0, v1);
                    }
                }
            }
        }
    }
}

// ---------------------------------------------------------------------------
// Prologue (single CTA, fp32): for all 4 layers compute
//   G_l = M_l @ W3hm_l (+hm_b), M_{l+1} = M_l @ E3_l (+eu_b), G2_l = M_{l+1} @ P3_l (+pm_b)
//   WaE1 = huW[0:64)@E1 ; WbE1 = huW[64:128)@E1 ; bU = hu_b@E1  (same for E2 -> V)
__global__ void __launch_bounds__(256) precompute_kernel(
    const float* __restrict__ ee_W, const float* __restrict__ ee_b,
    const float* __restrict__ hm_W, const float* __restrict__ hm_b,
    const float* __restrict__ hu_W, const float* __restrict__ hu_b,
    const float* __restrict__ eu_W, const float* __restrict__ eu_b,
    const float* __restrict__ pm_W, const float* __restrict__ pm_b,
    float* __restrict__ Gall, float* __restrict__ G2all,
    float* __restrict__ CW, float* __restrict__ CB)
{
    __shared__ float Ms[17 * 64];
    __shared__ float Mn[17 * 64];
    __shared__ float Bs[64 * 64];
    const int tid = threadIdx.x;

    for (int i = tid; i < 16 * 64; i += 256) Ms[i] = ee_W[i];
    if (tid < 64) Ms[16 * 64 + tid] = ee_b[tid];
    __syncthreads();

    for (int l = 0; l < 4; l++) {
        const float* W3hm = hm_W + (size_t)l * 320 * 64 + 256 * 64;
        const float* E1 = eu_W + (size_t)l * 192 * 64;
        const float* E2 = E1 + 64 * 64;
        const float* E3 = E1 + 128 * 64;
        const float* P3 = pm_W + (size_t)l * 192 * 64 + 128 * 64;
        const float* huW = hu_W + (size_t)l * 128 * 64;
        const float* hub = hu_b + l * 64;

        // G and M_next
        for (int i = tid; i < 17 * 64; i += 256) {
            const int r = i >> 6, c = i & 63;
            float accG = (r == 16) ? hm_b[l * 64 + c] : 0.0f;
            float accM = (r == 16) ? eu_b[l * 64 + c] : 0.0f;
            #pragma unroll 8
            for (int k = 0; k < 64; k++) {
                const float m = Ms[r * 64 + k];
                accG += m * W3hm[k * 64 + c];
                accM += m * E3[k * 64 + c];
            }
            Gall[l * 17 * 64 + i] = accG;
            Mn[i] = accM;
        }
        __syncthreads();
        // G2 from M_next
        for (int i = tid; i < 17 * 64; i += 256) {
            const int r = i >> 6, c = i & 63;
            float acc = (r == 16) ? pm_b[l * 64 + c] : 0.0f;
            #pragma unroll 8
            for (int k = 0; k < 64; k++) acc += Mn[r * 64 + k] * P3[k * 64 + c];
            G2all[l * 17 * 64 + i] = acc;
        }
        __syncthreads();
        for (int i = tid; i < 17 * 64; i += 256) Ms[i] = Mn[i];

        // Composites with E1
        __syncthreads();
        for (int i = tid; i < 64 * 64; i += 256) Bs[i] = E1[i];
        __syncthreads();
        for (int i = tid; i < 64 * 64; i += 256) {
            const int r = i >> 6, c = i & 63;
            float a0 = 0.0f, a1 = 0.0f;
            #pragma unroll 8
            for (int k = 0; k < 64; k++) {
                const float b = Bs[k * 64 + c];
                a0 += huW[r * 64 + k] * b;
                a1 += huW[(r + 64) * 64 + k] * b;
            }
            CW[(l * 4 + 0) * 4096 + i] = a0;
            CW[(l * 4 + 1) * 4096 + i] = a1;
        }
        if (tid < 64) {
            float acc = 0.0f;
            #pragma unroll 8
            for (int k = 0; k < 64; k++) acc += hub[k] * Bs[k * 64 + tid];
            CB[(l * 2 + 0) * 64 + tid] = acc;
        }
        // Composites with E2
        __syncthreads();
        for (int i = tid; i < 64 * 64; i += 256) Bs[i] = E2[i];
        __syncthreads();
        for (int i = tid; i < 64 * 64; i += 256) {
            const int r = i >> 6, c = i & 63;
            float a0 = 0.0f, a1 = 0.0f;
            #pragma unroll 8
            for (int k = 0; k < 64; k++) {
                const float b = Bs[k * 64 + c];
                a0 += huW[r * 64 + k] * b;
                a1 += huW[(r + 64) * 64 + k] * b;
            }
            CW[(l * 4 + 2) * 4096 + i] = a0;
            CW[(l * 4 + 3) * 4096 + i] = a1;
        }
        if (tid < 64) {
            float acc = 0.0f;
            #pragma unroll 8
            for (int k = 0; k < 64; k++) acc += hub[k] * Bs[k * 64 + tid];
            CB[(l * 2 + 1) * 64 + tid] = acc;
        }
        __syncthreads();
    }
}

// agg[rec[j]] += A[send[j]]  (64 wide). 8 threads per edge.
__global__ void __launch_bounds__(256) scatter64_kernel(
    const float* __restrict__ A, const int* __restrict__ send,
    const int* __restrict__ rec, float* __restrict__ agg)
{
    const int tid = threadIdx.x;
    const int e = blockIdx.x * 32 + (tid >> 3);
    const int part = (tid & 7) * 8;
    const int s = send[e];
    const int r = rec[e];
    const float* ap = A + (size_t)s * 64 + part;
    float* op = agg + (size_t)r * 64 + part;
    float4 v0 = *(const float4*)ap;
    float4 v1 = *(const float4*)(ap + 4);
    asm volatile("red.global.add.v4.f32 [%0], {%1, %2, %3, %4};"
                 :: "l"(op), "f"(v0.x), "f"(v0.y), "f"(v0.z), "f"(v0.w) : "memory");
    asm volatile("red.global.add.v4.f32 [%0], {%1, %2, %3, %4};"
                 :: "l"(op + 4), "f"(v1.x), "f"(v1.y), "f"(v1.z), "f"(v1.w) : "memory");
}

// Sagg[rec[j]] += e_in[j] (16 wide) and deg[rec[j]] += 1. 4 threads per edge.
__global__ void __launch_bounds__(256) scatter16deg_kernel(
    const float* __restrict__ e_in, const int* __restrict__ rec,
    float* __restrict__ Sagg, int* __restrict__ deg)
{
    const int tid = threadIdx.x;
    const int e = blockIdx.x * 64 + (tid >> 2);
    const int part = (tid & 3) * 4;
    const int r = rec[e];
    float4 v = *(const float4*)(e_in + (size_t)e * 16 + part);
    asm volatile("red.global.add.v4.f32 [%0], {%1, %2, %3, %4};"
                 :: "l"(Sagg + (size_t)r * 16 + part),
                    "f"(v.x), "f"(v.y), "f"(v.z), "f"(v.w) : "memory");
    if ((tid & 3) == 0) atomicAdd(&deg[r], 1);
}

// Small-K embedding (fp32): out[row] = x[row](K) @ W + b
template <int K>
__global__ void __launch_bounds__(256) embed_smallK_kernel(
    const float* __restrict__ x, const float* __restrict__ W,
    const float* __restrict__ bias, float* __restrict__ out, int nrows)
{
    __shared__ float Ws[K][64];
    __shared__ float bsm[64];
    const int tid = threadIdx.x;
    for (int i = tid; i < K * 64; i += 256) Ws[i / 64][i % 64] = W[i];
    if (tid < 64) bsm[tid] = bias[tid];
    __syncthreads();

    const int row = blockIdx.x * 128 + (tid >> 1);
    const int half = (tid & 1) * 32;
    if (row >= nrows) return;

    float xv[K];
    const float4* xp = (const float4*)(x + (size_t)row * K);
    #pragma unroll
    for (int i = 0; i < K / 4; i++) {
        float4 v = xp[i];
        xv[4 * i + 0] = v.x; xv[4 * i + 1] = v.y;
        xv[4 * i + 2] = v.z; xv[4 * i + 3] = v.w;
    }
    float acc[32];
    #pragma unroll
    for (int j = 0; j < 32; j++) acc[j] = bsm[half + j];
    #pragma unroll
    for (int k = 0; k < K; k++) {
        const float xk = xv[k];
        #pragma unroll
        for (int j = 0; j < 32; j++) acc[j] += xk * Ws[k][half + j];
    }
    float* op = out + (size_t)row * 64 + half;
    #pragma unroll
    for (int j = 0; j < 8; j++)
        ((float4*)op)[j] = make_float4(acc[4 * j], acc[4 * j + 1], acc[4 * j + 2], acc[4 * j + 3]);
}

// ---------------------------------------------------------------------------
extern "C" void kernel_launch(void* const* d_in, const int* in_sizes, int n_in,
                              void* d_out, int out_size)
{
    const float* h_in = (const float*)d_in[0];
    const float* e_in = (const float*)d_in[1];
    const float* p_in = (const float*)d_in[2];
    const int* ei = (const int*)d_in[3];
    const float* he_W = (const float*)d_in[4];
    const float* he_b = (const float*)d_in[5];
    const float* ee_W = (const float*)d_in[6];
    const float* ee_b = (const float*)d_in[7];
    const float* pe_W = (const float*)d_in[8];
    const float* pe_b = (const float*)d_in[9];
    const float* hm_W = (const float*)d_in[10];
    const float* hm_b = (const float*)d_in[11];
    const float* hu_W = (const float*)d_in[12];
    const float* hu_b = (const float*)d_in[13];
    const float* eu_W = (const float*)d_in[14];
    const float* eu_b = (const float*)d_in[15];
    const float* pm_W = (const float*)d_in[16];
    const float* pm_b = (const float*)d_in[17];
    const float* pu_W = (const float*)d_in[18];
    const float* pu_b = (const float*)d_in[19];

    const int* send = ei;
    const int* rec = ei + EE;

    float *h, *h2, *p, *U, *V, *A, *agg, *Sagg, *Gall, *G2all, *CW, *CB, *zero64;
    int* deg;
    cudaGetSymbolAddress((void**)&h, g_h);
    cudaGetSymbolAddress((void**)&h2, g_h2);
    cudaGetSymbolAddress((void**)&p, g_p);
    cudaGetSymbolAddress((void**)&U, g_U);
    cudaGetSymbolAddress((void**)&V, g_V);
    cudaGetSymbolAddress((void**)&A, g_A);
    cudaGetSymbolAddress((void**)&agg, g_agg);
    cudaGetSymbolAddress((void**)&Sagg, g_Sagg);
    cudaGetSymbolAddress((void**)&deg, g_deg);
    cudaGetSymbolAddress((void**)&Gall, g_Gall);
    cudaGetSymbolAddress((void**)&G2all, g_G2all);
    cudaGetSymbolAddress((void**)&CW, g_CW);
    cudaGetSymbolAddress((void**)&CB, g_CB);
    cudaGetSymbolAddress((void**)&zero64, g_zero64);

    const int SME = (256 * 72 * 2 + 64 * 72 * 2) * 2;  // 92160 B
    cudaFuncSetAttribute(mjgemm_kernel<0>, cudaFuncAttributeMaxDynamicSharedMemorySize, SME);
    cudaFuncSetAttribute(mjgemm_kernel<1>, cudaFuncAttributeMaxDynamicSharedMemorySize, SME);

    const int nodeGrid = (NN + 255) / 256;  // 196

    const Chunk CZ = {nullptr, 0, nullptr};
    const Job JZ = {};

    // ---- Prologue
    cudaMemsetAsync(U, 0, (size_t)NN * 64 * sizeof(float), 0);
    cudaMemsetAsync(V, 0, (size_t)NN * 64 * sizeof(float), 0);
    cudaMemsetAsync(Sagg, 0, (size_t)NN * 16 * sizeof(float), 0);
    cudaMemsetAsync(deg, 0, NN * sizeof(int), 0);
    scatter16deg_kernel<<<EE / 64, 256>>>(e_in, rec, Sagg, deg);
    precompute_kernel<<<1, 256>>>(ee_W, ee_b, hm_W, hm_b, hu_W, hu_b,
                                  eu_W, eu_b, pm_W, pm_b, Gall, G2all, CW, CB);

    // Embeddings
    mjgemm_kernel<0><<<dim3(nodeGrid, 1), 256, SME>>>(
        Job{Chunk{h_in, 128, he_W}, Chunk{h_in + 64, 128, he_W + 64 * 64}, CZ, he_b, h, 2},
        JZ, JZ, nullptr, nullptr, nullptr, NN);
    embed_smallK_kernel<16><<<(NN + 127) / 128, 256>>>(p_in, pe_W, pe_b, p, NN);

    float* hcur = h;
    float* hnxt = h2;

    for (int l = 0; l < 4; l++) {
        const float* hmW = hm_W + (size_t)l * 320 * 64;
        const float* huW = hu_W + (size_t)l * 128 * 64;
        const float* euW = eu_W + (size_t)l * 192 * 64;
        const float* pmW = pm_W + (size_t)l * 192 * 64;
        const float* puW = pu_W + (size_t)l * 128 * 64;
        const float* W3hm = hmW + 256 * 64;
        const float* E3 = euW + 128 * 64;
        const float* P3 = pmW + 128 * 64;
        const float* Gl = Gall + l * 17 * 64;
        const float* G2l = G2all + l * 17 * 64;

        // 1. h-msg: A = h@W1 + p@W2 + U@W3hm ; agg = deg*(h@W4+p@W5+V@W3hm + d) + Sagg@G
        mjgemm_kernel<1><<<dim3(nodeGrid, 2), 256, SME>>>(
            Job{Chunk{hcur, 64, hmW}, Chunk{p, 64, hmW + 64 * 64}, Chunk{U, 64, W3hm}, zero64, A, 3},
            Job{Chunk{hcur, 64, hmW + 128 * 64}, Chunk{p, 64, hmW + 192 * 64}, Chunk{V, 64, W3hm}, zero64, agg, 3},
            JZ, Sagg, Gl, deg, NN);
        // 2. agg += A[send]
        scatter64_kernel<<<EE / 32, 256>>>(A, send, rec, agg);
        // 3. merged: h' = h@Wa + agg@Wb + hu_b ; U' = U@E3 + h@WaE1 + agg@WbE1 + bU ; V' likewise
        mjgemm_kernel<0><<<dim3(nodeGrid, 3), 256, SME>>>(
            Job{Chunk{hcur, 64, huW}, Chunk{agg, 64, huW + 64 * 64}, CZ, hu_b + l * 64, hnxt, 2},
            Job{Chunk{U, 64, E3}, Chunk{hcur, 64, CW + (l * 4 + 0) * 4096}, Chunk{agg, 64, CW + (l * 4 + 1) * 4096}, CB + (l * 2 + 0) * 64, U, 3},
            Job{Chunk{V, 64, E3}, Chunk{hcur, 64, CW + (l * 4 + 2) * 4096}, Chunk{agg, 64, CW + (l * 4 + 3) * 4096}, CB + (l * 2 + 1) * 64, V, 3},
            nullptr, nullptr, nullptr, NN);
        // 4. p-msg: A = p@P1 + U@P3 ; agg = deg*(p@P2+V@P3 + d2) + Sagg@G2
        mjgemm_kernel<1><<<dim3(nodeGrid, 2), 256, SME>>>(
            Job{Chunk{p, 64, pmW}, Chunk{U, 64, P3}, CZ, zero64, A, 2},
            Job{Chunk{p, 64, pmW + 64 * 64}, Chunk{V, 64, P3}, CZ, zero64, agg, 2},
            JZ, Sagg, G2l, deg, NN);
        // 5. agg += A[send]
        scatter64_kernel<<<EE / 32, 256>>>(A, send, rec, agg);
        // 6. p update (last layer writes straight into d_out's p half)
        float* pout = (l == 3) ? ((float*)d_out + (size_t)NN * 64) : p;
        mjgemm_kernel<0><<<dim3(nodeGrid, 1), 256, SME>>>(
            Job{Chunk{p, 64, puW}, Chunk{agg, 64, puW + 64 * 64}, CZ, pu_b + l * 64, pout, 2},
            JZ, JZ, nullptr, nullptr, nullptr, NN);

        float* t = hcur; hcur = hnxt; hnxt = t;
    }

    // Output h half (hcur == g_h after 4 swaps)
    cudaMemcpyAsync(d_out, hcur, (size_t)NN * 64 * sizeof(float),
                    cudaMemcpyDeviceToDevice, 0);
}